// round 13
// baseline (speedup 1.0000x reference)
#include <cuda_runtime.h>
#include <math.h>
#include <stdint.h>

#define Bv    4
#define Tv    2048
#define Dv    1024
#define Hv    16
#define DHv   64
#define HALFv 32
#define MROWS (Bv*Tv)      // 8192
#define NQKV  (3*Dv)       // 3072
#define NKB   (Tv/64)      // 32 key tiles per bh

// ---- scratch (device globals) ----
__device__ float g_q[Bv*Hv*Tv*DHv];     // [b,h,t,dh] fp32 (pre-RoPE; rope fused into attn)
__device__ float g_k[Bv*Hv*Tv*DHv];     // [b,h,t,dh] fp32 (pre-RoPE; rope fused into pack)
__device__ float g_v[Bv*Hv*Tv*DHv];
__device__ float g_attn[MROWS*Dv];      // [b,t,d], tf32-rounded by attn epilogue
__device__ float g_xr[MROWS*Dv];        // tf32-rounded x
__device__ float g_wqkvr[NQKV*Dv];      // tf32-rounded W_qkv
__device__ float g_wprojr[Dv*Dv];       // tf32-rounded W_proj
// packed fragments, pairwise: [bh][kb][pi(32)][lane(32)] of uint4 (16KB/tile)
__device__ uint2 g_kpk[64*NKB*64*32];
__device__ uint2 g_vpk[64*NKB*64*32];

__device__ __forceinline__ uint32_t f2tf32(float f) {
    uint32_t u;
    asm("cvt.rna.tf32.f32 %0, %1;" : "=r"(u) : "f"(f));
    return u;
}

__device__ __forceinline__ void mma_tf32(
    float* c, uint32_t a0, uint32_t a1, uint32_t a2, uint32_t a3,
    uint32_t b0, uint32_t b1)
{
    asm volatile(
        "mma.sync.aligned.m16n8k8.row.col.f32.tf32.tf32.f32 "
        "{%0,%1,%2,%3}, {%4,%5,%6,%7}, {%8,%9}, {%0,%1,%2,%3};"
        : "+f"(c[0]), "+f"(c[1]), "+f"(c[2]), "+f"(c[3])
        : "r"(a0), "r"(a1), "r"(a2), "r"(a3), "r"(b0), "r"(b1));
}

__device__ __forceinline__ uint32_t smem_u32(const void* p) {
    uint32_t a;
    asm("{ .reg .u64 t; cvta.to.shared.u64 t, %1; cvt.u32.u64 %0, t; }"
        : "=r"(a) : "l"(p));
    return a;
}

#define LDSM4(r0, r1, r2, r3, addr) \
    asm volatile("ldmatrix.sync.aligned.m8n8.x4.shared.b16 {%0,%1,%2,%3}, [%4];" \
                 : "=r"(r0), "=r"(r1), "=r"(r2), "=r"(r3) : "r"(addr))

#define CP_ASYNC16(dst_u32, src) \
    asm volatile("cp.async.cg.shared.global [%0], [%1], 16;" \
                 :: "r"(dst_u32), "l"(src) : "memory")
#define CP_COMMIT() asm volatile("cp.async.commit_group;" ::: "memory")
#define CP_WAIT1()  asm volatile("cp.async.wait_group 1;" ::: "memory")
#define CP_WAIT0()  asm volatile("cp.async.wait_group 0;" ::: "memory")

// stage a contiguous 16KB tile into smem with 128 threads (8 x 16B each)
__device__ __forceinline__ void stage16k(uint32_t dst, const char* src, int tid) {
    #pragma unroll
    for (int p = 0; p < 8; p++)
        CP_ASYNC16(dst + tid*16 + p*2048, src + tid*16 + p*2048);
}

// ============================================================================
// Round fp32 -> tf32 (RNA), stored as fp32 bits.
// ============================================================================
__global__ void round_tf32(const float* __restrict__ in, float* __restrict__ out,
                           int n)
{
    int i = (blockIdx.x * blockDim.x + threadIdx.x) * 4;
    if (i >= n) return;
    float4 v = *(const float4*)(in + i);
    v.x = __uint_as_float(f2tf32(v.x));
    v.y = __uint_as_float(f2tf32(v.y));
    v.z = __uint_as_float(f2tf32(v.z));
    v.w = __uint_as_float(f2tf32(v.w));
    *(float4*)(out + i) = v;
}

// ============================================================================
// cp.async tf32 GEMM, 4 stages, TWO chunks per barrier (32 barriers total).
// C[M,N] = A[M,K]*Bw[N,K]^T, K=1024. Inputs pre-rounded to tf32.
// ============================================================================
#define GP        20
#define SSTRIDE   (2*128*GP)           // floats per stage = 5120
#define NSTAGE    4
#define GEMM_SMEM (NSTAGE*SSTRIDE*4)   // 81920 B
#define NCH       (Dv/16)              // 64

template<int MODE>
__global__ __launch_bounds__(256, 2)
void gemm_cp(const float* __restrict__ A, const float* __restrict__ Bw,
             float* __restrict__ C)
{
    extern __shared__ float smf[];
    const uint32_t sb32 = smem_u32(smf);

    const int tid  = threadIdx.x;
    const int wid  = tid >> 5, lane = tid & 31;
    const int gid  = lane >> 2, tg = lane & 3;
    const int wm   = (wid >> 2) * 64;
    const int wn   = (wid & 3) * 32;
    const int m0   = blockIdx.y * 128, n0 = blockIdx.x * 128;

    const int r0 = tid >> 2, c4 = (tid & 3) * 4;
    const float* gA0 = A  + (size_t)(m0 + r0) * Dv + c4;
    const float* gA1 = gA0 + (size_t)64 * Dv;
    const float* gB0 = Bw + (size_t)(n0 + r0) * Dv + c4;
    const float* gB1 = gB0 + (size_t)64 * Dv;
    const uint32_t dA0 = sb32 + (r0*GP + c4) * 4;
    const uint32_t dA1 = dA0 + 64*GP*4;
    const uint32_t dB0 = dA0 + 2560*4;
    const uint32_t dB1 = dB0 + 64*GP*4;

    const int lrow = lane & 7, lsel = lane >> 3;
    uint32_t a_addr[4], b_addr[2];
    {
        const int arow = wm + ((lsel & 1) ? 8 : 0) + lrow;
        const int acol = (lsel >> 1) * 4;
        #pragma unroll
        for (int mi = 0; mi < 4; mi++)
            a_addr[mi] = sb32 + ((arow + mi*16)*GP + acol) * 4;
        const int bcol = (lsel & 1) * 4;
        #pragma unroll
        for (int p = 0; p < 2; p++) {
            const int brow = wn + (p*2 + (lsel >> 1))*8 + lrow;
            b_addr[p] = sb32 + 2560*4 + (brow*GP + bcol) * 4;
        }
    }

    float acc[4][4][4];
    #pragma unroll
    for (int i = 0; i < 4; i++)
        #pragma unroll
        for (int j = 0; j < 4; j++)
            #pragma unroll
            for (int r = 0; r < 4; r++) acc[i][j][r] = 0.f;

    // prologue: stage chunks 0 and 1
    #pragma unroll
    for (int p = 0; p < 2; p++) {
        const uint32_t so = p * SSTRIDE * 4;
        const int ko = p * 16;
        CP_ASYNC16(dA0 + so, gA0 + ko);
        CP_ASYNC16(dA1 + so, gA1 + ko);
        CP_ASYNC16(dB0 + so, gB0 + ko);
        CP_ASYNC16(dB1 + so, gB1 + ko);
    }
    CP_COMMIT();

    for (int pc = 0; pc < NCH/2; ++pc) {
        CP_WAIT0();
        __syncthreads();          // chunks 2pc,2pc+1 visible; old stages readable->free

        // prefetch chunks 2pc+2, 2pc+3 into stages (2pc+2)&3, (2pc+3)&3
        if (2*pc + 2 < NCH) {
            #pragma unroll
            for (int p = 0; p < 2; p++) {
                const int ch = 2*pc + 2 + p;
                const uint32_t so = (ch & 3) * SSTRIDE * 4;
                const int ko = ch * 16;
                CP_ASYNC16(dA0 + so, gA0 + ko);
                CP_ASYNC16(dA1 + so, gA1 + ko);
                CP_ASYNC16(dB0 + so, gB0 + ko);
                CP_ASYNC16(dB1 + so, gB1 + ko);
            }
            CP_COMMIT();
        }

        // compute both chunks (4 k8 steps) with no intervening barrier
        #pragma unroll
        for (int half = 0; half < 2; half++) {
            const uint32_t stoff = ((2*pc + half) & 3) * SSTRIDE * 4;
            #pragma unroll
            for (int ks = 0; ks < 2; ks++) {
                const uint32_t ko = stoff + ks * 32;
                uint32_t af[4][4], bf[4][2];
                #pragma unroll
                for (int mi = 0; mi < 4; mi++)
                    LDSM4(af[mi][0], af[mi][1], af[mi][2], af[mi][3], a_addr[mi] + ko);
                #pragma unroll
                for (int p = 0; p < 2; p++)
                    LDSM4(bf[2*p][0], bf[2*p][1], bf[2*p+1][0], bf[2*p+1][1],
                          b_addr[p] + ko);
                #pragma unroll
                for (int mi = 0; mi < 4; mi++)
                    #pragma unroll
                    for (int ni = 0; ni < 4; ni++)
                        mma_tf32(acc[mi][ni],
                                 af[mi][0], af[mi][1], af[mi][2], af[mi][3],
                                 bf[ni][0], bf[ni][1]);
            }
        }
    }

    #pragma unroll
    for (int mi = 0; mi < 4; mi++) {
        #pragma unroll
        for (int half = 0; half < 2; half++) {
            const int m = m0 + wm + mi * 16 + gid + half * 8;
            const int bb = m >> 11, trow = m & (Tv - 1);
            #pragma unroll
            for (int ni = 0; ni < 4; ni++) {
                const int n = n0 + wn + ni * 8 + tg * 2;
                float2 val;
                val.x = acc[mi][ni][half * 2 + 0];
                val.y = acc[mi][ni][half * 2 + 1];
                if (MODE == 0) {
                    const int wh = n >> 10;
                    const int d  = n & (Dv - 1);
                    const int h  = d >> 6, dd = d & 63;
                    float* dst = ((wh == 0) ? g_q : (wh == 1) ? g_k : g_v)
                               + ((size_t)(bb * Hv + h) * Tv + trow) * DHv + dd;
                    *(float2*)dst = val;
                } else {
                    *(float2*)(C + (size_t)m * Dv + n) = val;
                }
            }
        }
    }
}

// ============================================================================
// Pack K (RoPE fused, tf32) and V into pairwise mma b-fragment order.
// ============================================================================
__global__ __launch_bounds__(256)
void pack_kv(const float* __restrict__ cosT, const float* __restrict__ sinT)
{
    const int kb = blockIdx.x, bh = blockIdx.y;
    const size_t base = ((size_t)(bh * NKB + kb)) * 2048;   // uint2 units
    const size_t rowbase = (size_t)bh * Tv + kb * 64;

    #pragma unroll
    for (int i = 0; i < 8; i++) {
        int e = threadIdx.x + i * 256;      // 0..2047
        int lane = e & 31, fi = e >> 5;
        int gid = lane >> 2, tg = lane & 3;
        int ks = fi >> 3, nf = fi & 7;

        // ---- K fragment with fused RoPE ----
        {
            const int trow = kb*64 + nf*8 + gid;
            const float* kp = g_k + (rowbase + nf*8 + gid) * DHv;
            const int dd = ks*8 + tg;
            float r0, r1;
            if (dd < HALFv) {
                float c0 = cosT[trow*HALFv + dd],     s0 = sinT[trow*HALFv + dd];
                float c1 = cosT[trow*HALFv + dd + 4], s1 = sinT[trow*HALFv + dd + 4];
                r0 = kp[dd]     * c0 - kp[dd + HALFv]     * s0;
                r1 = kp[dd + 4] * c1 - kp[dd + 4 + HALFv] * s1;
            } else {
                const int i0 = dd - HALFv;
                float c0 = cosT[trow*HALFv + i0],     s0 = sinT[trow*HALFv + i0];
                float c1 = cosT[trow*HALFv + i0 + 4], s1 = sinT[trow*HALFv + i0 + 4];
                r0 = kp[i0]     * s0 + kp[dd]     * c0;
                r1 = kp[i0 + 4] * s1 + kp[dd + 4] * c1;
            }
            const int pi = ks*4 + (nf >> 1);
            g_kpk[base + ((size_t)pi*32 + lane)*2 + (nf & 1)] =
                make_uint2(f2tf32(r0), f2tf32(r1));
        }

        // ---- V fragment ----
        {
            const float* vp = g_v + (rowbase + ks*8 + tg) * DHv + nf*8 + gid;
            const int pi = ks*4 + (nf >> 1);
            g_vpk[base + ((size_t)pi*32 + lane)*2 + (nf & 1)] =
                make_uint2(f2tf32(vp[0]), f2tf32(vp[4*DHv]));
        }
    }
}

// ============================================================================
// Flash attention: 4 warps x 32 q-rows, K/V cp.async-staged, RoPE on Q fused
// into the fragment build (the 16 elements per row are closed under the +/-32
// rotation pairing: partner of j is j+8). QK^T 2-term split, PV tf32.
// Smem 96KB: Qlo 32K @0, Ppk 32K @32768, Ksm 16K @65536, Vsm 16K @81920.
// ============================================================================
#define ATTN_SMEM (96*1024)

__global__ __launch_bounds__(128, 2)
void attn_mma(const float* __restrict__ cosT, const float* __restrict__ sinT)
{
    extern __shared__ char sm[];
    uint4*  Qlop = (uint4*)sm;                 // 32KB
    float4* Ppk  = (float4*)(sm + 32768);      // 32KB
    uint4*  Ksm  = (uint4*)(sm + 65536);       // 16KB
    uint4*  Vsm  = (uint4*)(sm + 81920);       // 16KB
    const uint32_t sb = smem_u32(sm);
    const uint32_t ksm_a = sb + 65536, vsm_a = sb + 81920;

    const int qb = (int)gridDim.x - 1 - (int)blockIdx.x;  // heavy tiles first
    const int bh = blockIdx.y;
    const int tid = threadIdx.x;
    const int w = tid >> 5, lane = tid & 31;
    const int gid = lane >> 2, tg = lane & 3;

    int rowA[2], rowB[2];
    #pragma unroll
    for (int mi = 0; mi < 2; mi++) {
        rowA[mi] = qb*128 + 32*w + 16*mi + gid;
        rowB[mi] = rowA[mi] + 8;
    }

    // ---- Q fragments with fused RoPE: hi -> registers, lo -> smem ----
    uint4 qh[2][8];
    #pragma unroll
    for (int mi = 0; mi < 2; mi++) {
        const float* qA = g_q + ((size_t)bh*Tv + rowA[mi]) * DHv + tg;
        const float* qB = qA + 8 * DHv;
        float qa[16], qbv[16];
        #pragma unroll
        for (int j = 0; j < 16; j++) { qa[j] = qA[4*j]; qbv[j] = qB[4*j]; }
        // RoPE: element j (dd = tg+4j < 32) pairs with j+8 (dd+32)
        #pragma unroll
        for (int j = 0; j < 8; j++) {
            const int dd = tg + 4*j;
            float c0 = cosT[rowA[mi]*HALFv + dd], s0 = sinT[rowA[mi]*HALFv + dd];
            float c1 = cosT[rowB[mi]*HALFv + dd], s1 = sinT[rowB[mi]*HALFv + dd];
            float a1 = qa[j],  a2 = qa[j+8];
            qa[j]   = a1*c0 - a2*s0;
            qa[j+8] = a1*s0 + a2*c0;
            float b1 = qbv[j], b2 = qbv[j+8];
            qbv[j]   = b1*c1 - b2*s1;
            qbv[j+8] = b1*s1 + b2*c1;
        }
        #pragma unroll
        for (int ks = 0; ks < 8; ks++) {
            float q0 = qa [2*ks    ] * 0.125f;
            float q1 = qbv[2*ks    ] * 0.125f;
            float q2 = qa [2*ks + 1] * 0.125f;
            float q3 = qbv[2*ks + 1] * 0.125f;
            uint32_t h0 = f2tf32(q0), h1 = f2tf32(q1);
            uint32_t h2 = f2tf32(q2), h3 = f2tf32(q3);
            qh[mi][ks] = make_uint4(h0, h1, h2, h3);
            Qlop[((w*2 + mi)*8 + ks)*32 + lane] =
                make_uint4(f2tf32(q0 - __uint_as_float(h0)),
                           f2tf32(q1 - __uint_as_float(h1)),
                           f2tf32(q2 - __uint_as_float(h2)),
                           f2tf32(q3 - __uint_as_float(h3)));
        }
    }

    float O[2][8][4];
    #pragma unroll
    for (int mi = 0; mi < 2; mi++)
        #pragma unroll
        for (int d = 0; d < 8; d++)
            #pragma unroll
            for (int r = 0; r < 4; r++) O[mi][d][r] = 0.f;
    float mA[2] = {-1e30f, -1e30f}, mB[2] = {-1e30f, -1e30f};
    float lA[2] = {0.f, 0.f},       lB[2] = {0.f, 0.f};

    const char* kbase = (const char*)g_kpk + (size_t)bh * (NKB * 16384);
    const char* vbase = (const char*)g_vpk + (size_t)bh * (NKB * 16384);
    const int niter = 2 * (qb + 1);

    // prologue: stage tile 0
    stage16k(ksm_a, kbase, tid); CP_COMMIT();
    stage16k(vsm_a, vbase, tid); CP_COMMIT();

    for (int j = 0; j < niter; j++) {
        const int k0g = j * 64;
        CP_WAIT1();            // K(j) landed (V(j) may be in flight)
        __syncthreads();       // Ksm visible to all warps

        // ---- S = Q K^T (2-term split), 2 m-frags ----
        float S[2][8][4];
        #pragma unroll
        for (int mi = 0; mi < 2; mi++)
            #pragma unroll
            for (int nf = 0; nf < 8; nf++)
                #pragma unroll
                for (int r = 0; r < 4; r++) S[mi][nf][r] = 0.f;
        #pragma unroll
        for (int ks = 0; ks < 8; ks++) {
            uint4 ql0 = Qlop[((w*2 + 0)*8 + ks)*32 + lane];
            uint4 ql1 = Qlop[((w*2 + 1)*8 + ks)*32 + lane];
            #pragma unroll
            for (int nf2 = 0; nf2 < 4; nf2++) {
                uint4 kf = Ksm[(ks*4 + nf2)*32 + lane];
                mma_tf32(S[0][2*nf2    ], qh[0][ks].x, qh[0][ks].y, qh[0][ks].z, qh[0][ks].w, kf.x, kf.y);
                mma_tf32(S[0][2*nf2    ], ql0.x, ql0.y, ql0.z, ql0.w, kf.x, kf.y);
                mma_tf32(S[0][2*nf2 + 1], qh[0][ks].x, qh[0][ks].y, qh[0][ks].z, qh[0][ks].w, kf.z, kf.w);
                mma_tf32(S[0][2*nf2 + 1], ql0.x, ql0.y, ql0.z, ql0.w, kf.z, kf.w);
                mma_tf32(S[1][2*nf2    ], qh[1][ks].x, qh[1][ks].y, qh[1][ks].z, qh[1][ks].w, kf.x, kf.y);
                mma_tf32(S[1][2*nf2    ], ql1.x, ql1.y, ql1.z, ql1.w, kf.x, kf.y);
                mma_tf32(S[1][2*nf2 + 1], qh[1][ks].x, qh[1][ks].y, qh[1][ks].z, qh[1][ks].w, kf.z, kf.w);
                mma_tf32(S[1][2*nf2 + 1], ql1.x, ql1.y, ql1.z, ql1.w, kf.z, kf.w);
            }
        }

        // ---- mask + online softmax + pack P (per m-frag) ----
        #pragma unroll
        for (int mi = 0; mi < 2; mi++) {
            float mxA = -1e30f, mxB = -1e30f;
            #pragma unroll
            for (int nf = 0; nf < 8; nf++) {
                const int cA = k0g + nf*8 + 2*tg, cB = cA + 1;
                if (cA > rowA[mi]) S[mi][nf][0] = -1e30f;
                if (cB > rowA[mi]) S[mi][nf][1] = -1e30f;
                if (cA > rowB[mi]) S[mi][nf][2] = -1e30f;
                if (cB > rowB[mi]) S[mi][nf][3] = -1e30f;
                mxA = fmaxf(mxA, fmaxf(S[mi][nf][0], S[mi][nf][1]));
                mxB = fmaxf(mxB, fmaxf(S[mi][nf][2], S[mi][nf][3]));
            }
            mxA = fmaxf(mxA, __shfl_xor_sync(0xffffffffu, mxA, 1));
            mxA = fmaxf(mxA, __shfl_xor_sync(0xffffffffu, mxA, 2));
            mxB = fmaxf(mxB, __shfl_xor_sync(0xffffffffu, mxB, 1));
            mxB = fmaxf(mxB, __shfl_xor_sync(0xffffffffu, mxB, 2));
            const float mnA = fmaxf(mA[mi], mxA), mnB = fmaxf(mB[mi], mxB);
            const float corrA = __expf(mA[mi] - mnA), corrB = __expf(mB[mi] - mnB);

            float sA = 0.f, sB = 0.f;
            #pragma unroll
            for (int nf = 0; nf < 8; nf++) {
                const int cA = k0g + nf*8 + 2*tg, cB = cA + 1;
                float e0 = __expf(S[mi][nf][0] - mnA);
                float e1 = __expf(S[mi][nf][1] - mnA);
                float e2 = __expf(S[mi][nf][2] - mnB);
                float e3 = __expf(S[mi][nf][3] - mnB);
                sA += e0 + e1; sB += e2 + e3;
                if (cA == rowA[mi]) e0 = 0.f;
                if (cB == rowA[mi]) e1 = 0.f;
                if (cA == rowB[mi]) e2 = 0.f;
                if (cB == rowB[mi]) e3 = 0.f;
                {
                    const int c0p = 2*tg;
                    char* b = (char*)&Ppk[((w*2 + mi)*8 + nf)*32 + 4*gid + (c0p & 3)];
                    *(uint2*)(b + ((c0p < 4) ? 0 : 8)) = make_uint2(f2tf32(e0), f2tf32(e2));
                }
                {
                    const int c1p = 2*tg + 1;
                    char* b = (char*)&Ppk[((w*2 + mi)*8 + nf)*32 + 4*gid + (c1p & 3)];
                    *(uint2*)(b + ((c1p < 4) ? 0 : 8)) = make_uint2(f2tf32(e1), f2tf32(e3));
                }
            }
            sA += __shfl_xor_sync(0xffffffffu, sA, 1);
            sA += __shfl_xor_sync(0xffffffffu, sA, 2);
            sB += __shfl_xor_sync(0xffffffffu, sB, 1);
            sB += __shfl_xor_sync(0xffffffffu, sB, 2);
            lA[mi] = lA[mi] * corrA + sA;  mA[mi] = mnA;
            lB[mi] = lB[mi] * corrB + sB;  mB[mi] = mnB;
            #pragma unroll
            for (int d = 0; d < 8; d++) {
                O[mi][d][0] *= corrA; O[mi][d][1] *= corrA;
                O[mi][d][2] *= corrB; O[mi][d][3] *= corrB;
            }
        }

        CP_WAIT0();            // V(j) landed
        __syncthreads();       // Ksm free + Vsm visible (+ Ppk ordering)
        if (j + 1 < niter) {   // prefetch K(j+1) while PV runs
            stage16k(ksm_a, kbase + (size_t)(j + 1) * 16384, tid);
            CP_COMMIT();
        }

        // ---- O += P V (tf32), 2 m-frags ----
        #pragma unroll
        for (int cs = 0; cs < 8; cs++) {
            uint4 a0 = *(const uint4*)&Ppk[((w*2 + 0)*8 + cs)*32 + lane];
            uint4 a1 = *(const uint4*)&Ppk[((w*2 + 1)*8 + cs)*32 + lane];
            #pragma unroll
            for (int df2 = 0; df2 < 4; df2++) {
                uint4 b = Vsm[(cs*4 + df2)*32 + lane];
                mma_tf32(O[0][2*df2    ], a0.x, a0.y, a0.z, a0.w, b.x, b.y);
                mma_tf32(O[0][2*df2 + 1], a0.x, a0.y, a0.z, a0.w, b.z, b.w);
                mma_tf32(O[1][2*df2    ], a1.x, a1.y, a1.z, a1.w, b.x, b.y);
                mma_tf32(O[1][2*df2 + 1], a1.x, a1.y, a1.z, a1.w, b.z, b.w);
            }
        }

        __syncthreads();       // Vsm free
        if (j + 1 < niter) {   // prefetch V(j+1)
            stage16k(vsm_a, vbase + (size_t)(j + 1) * 16384, tid);
            CP_COMMIT();
        }
    }

    // ---- epilogue (round to tf32 for the proj GEMM) ----
    const int bb = bh >> 4, h = bh & 15;
    #pragma unroll
    for (int mi = 0; mi < 2; mi++) {
        const float inv0 = 1.f / lA[mi], inv1 = 1.f / lB[mi];
        #pragma unroll
        for (int df = 0; df < 8; df++) {
            const int col = h*64 + df*8 + 2*tg;
            float2 vA, vB;
            vA.x = __uint_as_float(f2tf32(O[mi][df][0] * inv0));
            vA.y = __uint_as_float(f2tf32(O[mi][df][1] * inv0));
            vB.x = __uint_as_float(f2tf32(O[mi][df][2] * inv1));
            vB.y = __uint_as_float(f2tf32(O[mi][df][3] * inv1));
            *(float2*)&g_attn[((size_t)bb*Tv + rowA[mi]) * Dv + col] = vA;
            *(float2*)&g_attn[((size_t)bb*Tv + rowB[mi]) * Dv + col] = vB;
        }
    }
}

// ============================================================================
extern "C" void kernel_launch(void* const* d_in, const int* in_sizes, int n_in,
                              void* d_out, int out_size)
{
    const float* x     = (const float*)d_in[0];
    const float* cosT  = (const float*)d_in[1];
    const float* sinT  = (const float*)d_in[2];
    const float* Wqkv  = (const float*)d_in[3];
    const float* Wproj = (const float*)d_in[4];

    float *attn_ptr, *xr_ptr, *wqkvr_ptr, *wprojr_ptr;
    cudaGetSymbolAddress((void**)&attn_ptr,   g_attn);
    cudaGetSymbolAddress((void**)&xr_ptr,     g_xr);
    cudaGetSymbolAddress((void**)&wqkvr_ptr,  g_wqkvr);
    cudaGetSymbolAddress((void**)&wprojr_ptr, g_wprojr);

    cudaFuncSetAttribute(attn_mma, cudaFuncAttributeMaxDynamicSharedMemorySize, ATTN_SMEM);
    cudaFuncSetAttribute(gemm_cp<0>, cudaFuncAttributeMaxDynamicSharedMemorySize, GEMM_SMEM);
    cudaFuncSetAttribute(gemm_cp<1>, cudaFuncAttributeMaxDynamicSharedMemorySize, GEMM_SMEM);

    // 0) pre-round GEMM inputs to tf32
    round_tf32<<<MROWS*Dv/1024, 256>>>(x, xr_ptr, MROWS*Dv);
    round_tf32<<<NQKV*Dv/1024, 256>>>(Wqkv, wqkvr_ptr, NQKV*Dv);
    round_tf32<<<Dv*Dv/1024, 256>>>(Wproj, wprojr_ptr, Dv*Dv);

    // 1) QKV projection, scattered into [b,h,t,dh]
    gemm_cp<0><<<dim3(NQKV/128, MROWS/128), 256, GEMM_SMEM>>>(xr_ptr, wqkvr_ptr, nullptr);
    // 2) pack K (rope fused) / V into pairwise fragment order
    pack_kv<<<dim3(NKB, Bv*Hv), 256>>>(cosT, sinT);
    // 3) causal attention (rope-q fused, cp.async-staged K/V)
    attn_mma<<<dim3(Tv/128, Bv*Hv), 128, ATTN_SMEM>>>(cosT, sinT);
    // 4) output projection -> d_out
    gemm_cp<1><<<dim3(Dv/128, MROWS/128), 256, GEMM_SMEM>>>(attn_ptr, wprojr_ptr, (float*)d_out);
}